// round 1
// baseline (speedup 1.0000x reference)
#include <cuda_runtime.h>
#include <math.h>

#define N_POS 256
#define D_DIM 128
#define N_HEADS 4
#define C_DIM 32
#define ROWS (N_POS * N_POS)   // 65536

#define BR 64
#define ZSTR 132
#define WSTR 132

// Scratch (static device arrays; no runtime allocation)
__device__ float g_q[N_POS * N_HEADS * N_POS * C_DIM];   // [i][h][j][c]
__device__ float g_k[N_POS * N_HEADS * N_POS * C_DIM];
__device__ float g_v[N_POS * N_HEADS * N_POS * C_DIM];
__device__ float g_g[ROWS * D_DIM];                      // [row][h*32+c]
__device__ float g_og[ROWS * D_DIM];                     // gated attn out
__device__ float g_trib[N_HEADS * ROWS];                 // [h][q*256+k]

// ---------------------------------------------------------------------------
// Kernel 1: LayerNorm + projections (q,k,v,g) + triangle bias
// grid: 1024 blocks of 64 rows, 256 threads
// ---------------------------------------------------------------------------
__global__ __launch_bounds__(256) void k_proj(
    const float* __restrict__ Z_raw,
    const float* __restrict__ ln_w, const float* __restrict__ ln_b,
    const float* __restrict__ w_b,
    const float* __restrict__ wq, const float* __restrict__ wk,
    const float* __restrict__ wv, const float* __restrict__ wg)
{
    extern __shared__ float sm[];
    float* zn = sm;                    // [BR][ZSTR]
    float* ws = sm + BR * ZSTR;        // [128][WSTR]
    const int tid  = threadIdx.x;
    const int row0 = blockIdx.x * BR;
    const int warp = tid >> 5, lane = tid & 31;

    // --- LayerNorm into smem (8 warps x 8 rows each) ---
    for (int r = warp; r < BR; r += 8) {
        const float4 x = ((const float4*)(Z_raw + (size_t)(row0 + r) * D_DIM))[lane];
        float s  = x.x + x.y + x.z + x.w;
        float ss = x.x * x.x + x.y * x.y + x.z * x.z + x.w * x.w;
        #pragma unroll
        for (int o = 16; o > 0; o >>= 1) {
            s  += __shfl_xor_sync(0xffffffffu, s, o);
            ss += __shfl_xor_sync(0xffffffffu, ss, o);
        }
        const float mu  = s * (1.0f / 128.0f);
        const float inv = rsqrtf(ss * (1.0f / 128.0f) - mu * mu + 1e-5f);
        const int c = lane * 4;
        float* zr = zn + r * ZSTR + c;
        zr[0] = (x.x - mu) * inv * __ldg(ln_w + c + 0) + __ldg(ln_b + c + 0);
        zr[1] = (x.y - mu) * inv * __ldg(ln_w + c + 1) + __ldg(ln_b + c + 1);
        zr[2] = (x.z - mu) * inv * __ldg(ln_w + c + 2) + __ldg(ln_b + c + 2);
        zr[3] = (x.w - mu) * inv * __ldg(ln_w + c + 3) + __ldg(ln_b + c + 3);
    }
    __syncthreads();

    // --- triangle bias: trib[h][pos] = zn[pos] . w_b[:,h] ---
    {
        const int r = tid >> 2, h = tid & 3;
        float acc = 0.0f;
        #pragma unroll 8
        for (int kk = 0; kk < D_DIM; kk++)
            acc = fmaf(zn[r * ZSTR + kk], __ldg(w_b + kk * N_HEADS + h), acc);
        g_trib[h * ROWS + row0 + r] = acc;
    }

    // --- GEMM: [64 x 128] @ [128 x 128] for each of wq,wk,wv,wg ---
    const int ty = tid >> 4, tx = tid & 15;
    const float* Wmats[4] = { wq, wk, wv, wg };
    for (int nt = 0; nt < 4; nt++) {
        __syncthreads();
        const float sc = (nt == 0) ? 0.17677669529663687f : 1.0f;  // c^-0.5 into q
        const float4* Wsrc = (const float4*)Wmats[nt];
        for (int idx = tid; idx < D_DIM * 32; idx += 256) {
            const int kk = idx >> 5, c4 = idx & 31;
            const float4 w4 = __ldg(Wsrc + idx);
            float* wr = ws + kk * WSTR + c4 * 4;
            wr[0] = w4.x * sc; wr[1] = w4.y * sc; wr[2] = w4.z * sc; wr[3] = w4.w * sc;
        }
        __syncthreads();

        float acc[4][8];
        #pragma unroll
        for (int i = 0; i < 4; i++)
            #pragma unroll
            for (int j = 0; j < 8; j++) acc[i][j] = 0.0f;

        for (int kk = 0; kk < D_DIM; kk++) {
            float a[4], b[8];
            #pragma unroll
            for (int i = 0; i < 4; i++) a[i] = zn[(ty * 4 + i) * ZSTR + kk];
            #pragma unroll
            for (int j = 0; j < 8; j++) b[j] = ws[kk * WSTR + tx * 8 + j];
            #pragma unroll
            for (int i = 0; i < 4; i++)
                #pragma unroll
                for (int j = 0; j < 8; j++) acc[i][j] = fmaf(a[i], b[j], acc[i][j]);
        }

        #pragma unroll
        for (int i = 0; i < 4; i++) {
            const int grow = row0 + ty * 4 + i;
            #pragma unroll
            for (int j = 0; j < 8; j++) {
                const int col = tx * 8 + j;
                if (nt < 3) {
                    const int ip = grow >> 8, jp = grow & 255;
                    const int h = col >> 5, c = col & 31;
                    float* dst = (nt == 0) ? g_q : (nt == 1) ? g_k : g_v;
                    dst[((ip * N_HEADS + h) * N_POS + jp) * C_DIM + c] = acc[i][j];
                } else {
                    g_g[(size_t)grow * D_DIM + col] = acc[i][j];
                }
            }
        }
    }
}

// ---------------------------------------------------------------------------
// Kernel 2: attention per (i,h). 128 threads, warp-per-query.
// grid: (256, 4)
// ---------------------------------------------------------------------------
__global__ __launch_bounds__(128) void k_attn(
    const float* __restrict__ Z_mask, const float* __restrict__ bg)
{
    extern __shared__ float sm[];
    float* qs = sm;                       // [256][33]
    float* ks = qs + N_POS * 33;
    float* vs = ks + N_POS * 33;
    float* ps = vs + N_POS * 33;          // [4][256]
    float* ms = ps + 4 * N_POS;           // [256]
    const int i = blockIdx.x, h = blockIdx.y;
    const int tid = threadIdx.x;

    const size_t base = (size_t)(i * N_HEADS + h) * N_POS * C_DIM;
    for (int idx = tid; idx < N_POS * C_DIM; idx += 128) {
        const int j = idx >> 5, c = idx & 31;
        qs[j * 33 + c] = g_q[base + idx];
        ks[j * 33 + c] = g_k[base + idx];
        vs[j * 33 + c] = g_v[base + idx];
    }
    for (int kk = tid; kk < N_POS; kk += 128)
        ms[kk] = 1e9f * (__ldg(Z_mask + i * N_POS + kk) - 1.0f);
    __syncthreads();

    const int warp = tid >> 5, lane = tid & 31;
    const float* trib = g_trib + (size_t)h * ROWS;
    const float bghc = __ldg(bg + h * C_DIM + lane);
    float* pw = ps + warp * N_POS;

    for (int q = warp; q < N_POS; q += 4) {
        const float* tq   = trib + q * N_POS;
        const float* qrow = qs + q * 33;
        float lg[8];
        #pragma unroll
        for (int m = 0; m < 8; m++) {
            const int kk = lane + m * 32;
            const float* krow = ks + kk * 33;
            float acc = 0.0f;
            #pragma unroll
            for (int c = 0; c < 32; c++)
                acc = fmaf(qrow[c], krow[c], acc);
            lg[m] = acc + ms[kk] + __ldg(tq + kk);
        }
        float mx = lg[0];
        #pragma unroll
        for (int m = 1; m < 8; m++) mx = fmaxf(mx, lg[m]);
        #pragma unroll
        for (int o = 16; o > 0; o >>= 1)
            mx = fmaxf(mx, __shfl_xor_sync(0xffffffffu, mx, o));
        float sum = 0.0f;
        #pragma unroll
        for (int m = 0; m < 8; m++) { lg[m] = __expf(lg[m] - mx); sum += lg[m]; }
        #pragma unroll
        for (int o = 16; o > 0; o >>= 1)
            sum += __shfl_xor_sync(0xffffffffu, sum, o);
        #pragma unroll
        for (int m = 0; m < 8; m++) pw[lane + m * 32] = lg[m];
        __syncwarp();
        float acc = 0.0f;
        for (int kk = 0; kk < N_POS; kk++)
            acc = fmaf(pw[kk], vs[kk * 33 + lane], acc);
        const float o = acc / sum;
        const int grow = i * N_POS + q;
        const float gv = g_g[(size_t)grow * D_DIM + h * C_DIM + lane] + bghc;
        const float gate = 1.0f / (1.0f + __expf(-gv));
        g_og[(size_t)grow * D_DIM + h * C_DIM + lane] = o * gate;
        __syncwarp();
    }
}

// ---------------------------------------------------------------------------
// Kernel 3: output projection + bias + residual
// ---------------------------------------------------------------------------
__global__ __launch_bounds__(256) void k_out(
    const float* __restrict__ Z_raw, const float* __restrict__ wo,
    const float* __restrict__ out_bias, float* __restrict__ out)
{
    extern __shared__ float sm[];
    float* os = sm;                    // [BR][ZSTR]
    float* ws = sm + BR * ZSTR;        // [128][WSTR]
    const int tid  = threadIdx.x;
    const int row0 = blockIdx.x * BR;

    for (int idx = tid; idx < BR * 32; idx += 256) {
        const int r = idx >> 5, c4 = idx & 31;
        const float4 v = ((const float4*)g_og)[(size_t)(row0 + r) * 32 + c4];
        float* orow = os + r * ZSTR + c4 * 4;
        orow[0] = v.x; orow[1] = v.y; orow[2] = v.z; orow[3] = v.w;
    }
    for (int idx = tid; idx < D_DIM * 32; idx += 256) {
        const int kk = idx >> 5, c4 = idx & 31;
        const float4 w4 = __ldg((const float4*)wo + idx);
        float* wr = ws + kk * WSTR + c4 * 4;
        wr[0] = w4.x; wr[1] = w4.y; wr[2] = w4.z; wr[3] = w4.w;
    }
    __syncthreads();

    const int ty = tid >> 4, tx = tid & 15;
    float acc[4][8];
    #pragma unroll
    for (int i = 0; i < 4; i++)
        #pragma unroll
        for (int j = 0; j < 8; j++) acc[i][j] = 0.0f;

    for (int kk = 0; kk < D_DIM; kk++) {
        float a[4], b[8];
        #pragma unroll
        for (int i = 0; i < 4; i++) a[i] = os[(ty * 4 + i) * ZSTR + kk];
        #pragma unroll
        for (int j = 0; j < 8; j++) b[j] = ws[kk * WSTR + tx * 8 + j];
        #pragma unroll
        for (int i = 0; i < 4; i++)
            #pragma unroll
            for (int j = 0; j < 8; j++) acc[i][j] = fmaf(a[i], b[j], acc[i][j]);
    }

    #pragma unroll
    for (int i = 0; i < 4; i++) {
        const int grow = row0 + ty * 4 + i;
        #pragma unroll
        for (int j = 0; j < 8; j++) {
            const int col = tx * 8 + j;
            out[(size_t)grow * D_DIM + col] =
                acc[i][j] + __ldg(out_bias + col) + Z_raw[(size_t)grow * D_DIM + col];
        }
    }
}

// ---------------------------------------------------------------------------
extern "C" void kernel_launch(void* const* d_in, const int* in_sizes, int n_in,
                              void* d_out, int out_size)
{
    (void)in_sizes; (void)n_in; (void)out_size;
    const float* Z_raw    = (const float*)d_in[0];
    const float* Z_mask   = (const float*)d_in[1];
    const float* ln_w     = (const float*)d_in[2];
    const float* ln_b     = (const float*)d_in[3];
    const float* w_b      = (const float*)d_in[4];
    const float* wq       = (const float*)d_in[5];
    const float* wk       = (const float*)d_in[6];
    const float* wv       = (const float*)d_in[7];
    const float* wg       = (const float*)d_in[8];
    const float* bg       = (const float*)d_in[9];
    const float* wo       = (const float*)d_in[10];
    const float* out_bias = (const float*)d_in[11];
    float* out = (float*)d_out;

    const int smem_proj = (BR * ZSTR + D_DIM * WSTR) * 4;                 // 101376
    const int smem_attn = (3 * N_POS * 33 + 4 * N_POS + N_POS) * 4;      // 106496

    cudaFuncSetAttribute(k_proj, cudaFuncAttributeMaxDynamicSharedMemorySize, smem_proj);
    cudaFuncSetAttribute(k_attn, cudaFuncAttributeMaxDynamicSharedMemorySize, smem_attn);
    cudaFuncSetAttribute(k_out,  cudaFuncAttributeMaxDynamicSharedMemorySize, smem_proj);

    k_proj<<<ROWS / BR, 256, smem_proj>>>(Z_raw, ln_w, ln_b, w_b, wq, wk, wv, wg);
    k_attn<<<dim3(N_POS, N_HEADS), 128, smem_attn>>>(Z_mask, bg);
    k_out<<<ROWS / BR, 256, smem_proj>>>(Z_raw, wo, out_bias, out);
}

// round 4
// speedup vs baseline: 3.9596x; 3.9596x over previous
#include <cuda_runtime.h>
#include <cuda_bf16.h>
#include <math.h>

#define N_POS 256
#define D_DIM 128
#define N_HEADS 4
#define C_DIM 32
#define ROWS (N_POS * N_POS)   // 65536

// ---------------- scratch (static device arrays) ----------------
__device__ __nv_bfloat16 g_qb[N_POS * N_HEADS * N_POS * C_DIM];   // [i][h][j][c]
__device__ __nv_bfloat16 g_kb[N_POS * N_HEADS * N_POS * C_DIM];
__device__ __nv_bfloat16 g_vb[N_POS * N_HEADS * N_POS * C_DIM];
__device__ float         g_g [ROWS * D_DIM];                      // gate preact [row][h*32+c]
__device__ __nv_bfloat16 g_ogb[ROWS * D_DIM];                     // gated attn out (bf16)
__device__ float         g_trib[N_HEADS * ROWS];                  // [h][q*256+k]
__device__ __nv_bfloat16 g_wT[4][D_DIM * D_DIM];                  // q,k,v,g as [n][k] bf16
__device__ __nv_bfloat16 g_woT[D_DIM * D_DIM];                    // [d][hc] bf16

// ---------------- mma helper ----------------
__device__ __forceinline__ void mma_bf16(float* c, const unsigned* a, const unsigned* b) {
    asm volatile(
        "mma.sync.aligned.m16n8k16.row.col.f32.bf16.bf16.f32 "
        "{%0,%1,%2,%3}, {%4,%5,%6,%7}, {%8,%9}, {%0,%1,%2,%3};\n"
        : "+f"(c[0]), "+f"(c[1]), "+f"(c[2]), "+f"(c[3])
        : "r"(a[0]), "r"(a[1]), "r"(a[2]), "r"(a[3]), "r"(b[0]), "r"(b[1]));
}

__device__ __forceinline__ unsigned pack_bf16(float lo, float hi) {
    __nv_bfloat162 t = __float22bfloat162_rn(make_float2(lo, hi));
    return *(unsigned*)&t;
}

// ---------------- kernel 0: weight transpose to bf16 ----------------
__global__ __launch_bounds__(256) void k_setup(
    const float* __restrict__ wq, const float* __restrict__ wk,
    const float* __restrict__ wv, const float* __restrict__ wg,
    const float* __restrict__ wo)
{
    int idx = blockIdx.x * 256 + threadIdx.x;
    if (idx >= 5 * 16384) return;
    const int m = idx >> 14, r = idx & 16383;
    const int k = r >> 7, n = r & 127;
    const float* src = (m == 0) ? wq : (m == 1) ? wk : (m == 2) ? wv : (m == 3) ? wg : wo;
    float v = src[r];
    if (m == 0) v *= 0.17677669529663687f;   // c^-0.5 folded into wq
    __nv_bfloat16 bv = __float2bfloat16(v);
    if (m < 4) g_wT[m][n * 128 + k] = bv;
    else       g_woT[n * 128 + k] = bv;
}

// ---------------- kernel 1: LN + 4 projections + triangle bias ----------------
#define SA 136   // bf16 row stride
__global__ __launch_bounds__(256) void k_proj(
    const float* __restrict__ Z_raw,
    const float* __restrict__ ln_w, const float* __restrict__ ln_b,
    const float* __restrict__ w_b)
{
    extern __shared__ __nv_bfloat16 smb[];
    __nv_bfloat16* zn = smb;                 // [64][SA]
    __nv_bfloat16* ws = smb + 64 * SA;       // [128][SA]
    const int tid  = threadIdx.x;
    const int row0 = blockIdx.x * 64;
    const int warp = tid >> 5, lane = tid & 31;

    // --- LayerNorm -> bf16 smem ---
    for (int r = warp; r < 64; r += 8) {
        const float4 x = ((const float4*)(Z_raw + (size_t)(row0 + r) * D_DIM))[lane];
        float s  = x.x + x.y + x.z + x.w;
        float ss = x.x * x.x + x.y * x.y + x.z * x.z + x.w * x.w;
        #pragma unroll
        for (int o = 16; o > 0; o >>= 1) {
            s  += __shfl_xor_sync(0xffffffffu, s, o);
            ss += __shfl_xor_sync(0xffffffffu, ss, o);
        }
        const float mu  = s * (1.0f / 128.0f);
        const float inv = rsqrtf(ss * (1.0f / 128.0f) - mu * mu + 1e-5f);
        const int c = lane * 4;
        float v0 = (x.x - mu) * inv * __ldg(ln_w + c + 0) + __ldg(ln_b + c + 0);
        float v1 = (x.y - mu) * inv * __ldg(ln_w + c + 1) + __ldg(ln_b + c + 1);
        float v2 = (x.z - mu) * inv * __ldg(ln_w + c + 2) + __ldg(ln_b + c + 2);
        float v3 = (x.w - mu) * inv * __ldg(ln_w + c + 3) + __ldg(ln_b + c + 3);
        __nv_bfloat162* zr = (__nv_bfloat162*)(zn + r * SA + c);
        zr[0] = __float22bfloat162_rn(make_float2(v0, v1));
        zr[1] = __float22bfloat162_rn(make_float2(v2, v3));
    }
    __syncthreads();

    // --- triangle bias ---
    {
        const int r = tid >> 2, h = tid & 3;
        float acc = 0.0f;
        #pragma unroll 8
        for (int kk = 0; kk < D_DIM; kk++)
            acc = fmaf(__bfloat162float(zn[r * SA + kk]), __ldg(w_b + kk * N_HEADS + h), acc);
        g_trib[h * ROWS + row0 + r] = acc;
    }

    // --- A fragments (reused across all 4 weight matrices) ---
    const int warp_m = warp & 3, warp_n = warp >> 2;
    const int r0 = warp_m * 16 + (lane >> 2);
    const int r1 = r0 + 8;
    unsigned afr[8][4];
    #pragma unroll
    for (int kt = 0; kt < 8; kt++) {
        const __nv_bfloat16* a0 = zn + r0 * SA + kt * 16 + (lane & 3) * 2;
        const __nv_bfloat16* a1 = zn + r1 * SA + kt * 16 + (lane & 3) * 2;
        afr[kt][0] = *(const unsigned*)a0;
        afr[kt][1] = *(const unsigned*)a1;
        afr[kt][2] = *(const unsigned*)(a0 + 8);
        afr[kt][3] = *(const unsigned*)(a1 + 8);
    }

    for (int m = 0; m < 4; m++) {
        __syncthreads();
        // load W^T [128][128] bf16 -> smem (vectorized, coalesced)
        const __nv_bfloat16* Wsrc = g_wT[m];
        for (int idx = tid; idx < 2048; idx += 256) {
            const int n = idx >> 4, seg = idx & 15;
            *(uint4*)(ws + n * SA + seg * 8) = *(const uint4*)(Wsrc + n * 128 + seg * 8);
        }
        __syncthreads();

        float acc[8][4];
        #pragma unroll
        for (int nt = 0; nt < 8; nt++)
            #pragma unroll
            for (int j = 0; j < 4; j++) acc[nt][j] = 0.0f;

        #pragma unroll
        for (int kt = 0; kt < 8; kt++) {
            #pragma unroll
            for (int nt = 0; nt < 8; nt++) {
                const __nv_bfloat16* bp =
                    ws + (warp_n * 64 + nt * 8 + (lane >> 2)) * SA + kt * 16 + (lane & 3) * 2;
                unsigned b[2] = { *(const unsigned*)bp, *(const unsigned*)(bp + 8) };
                mma_bf16(acc[nt], afr[kt], b);
            }
        }

        // epilogue
        const int gr0 = row0 + r0, gr1 = row0 + r1;
        #pragma unroll
        for (int nt = 0; nt < 8; nt++) {
            const int col = warp_n * 64 + nt * 8 + (lane & 3) * 2;
            if (m < 3) {
                const int h = col >> 5, c = col & 31;
                __nv_bfloat16* dst = (m == 0) ? g_qb : (m == 1) ? g_kb : g_vb;
                const int i0 = gr0 >> 8, j0 = gr0 & 255;
                const int i1 = gr1 >> 8, j1 = gr1 & 255;
                *(__nv_bfloat162*)(dst + ((i0 * 4 + h) * 256 + j0) * 32 + c) =
                    __float22bfloat162_rn(make_float2(acc[nt][0], acc[nt][1]));
                *(__nv_bfloat162*)(dst + ((i1 * 4 + h) * 256 + j1) * 32 + c) =
                    __float22bfloat162_rn(make_float2(acc[nt][2], acc[nt][3]));
            } else {
                *(float2*)(g_g + (size_t)gr0 * D_DIM + col) = make_float2(acc[nt][0], acc[nt][1]);
                *(float2*)(g_g + (size_t)gr1 * D_DIM + col) = make_float2(acc[nt][2], acc[nt][3]);
            }
        }
    }
}

// ---------------- kernel 2: attention per (i,h), flash-style in registers ----------------
#define SQ 40     // Qs/Ks bf16 row stride
#define SV 264    // VsT bf16 row stride
__global__ __launch_bounds__(128) void k_attn(
    const float* __restrict__ Z_mask, const float* __restrict__ bg)
{
    extern __shared__ __nv_bfloat16 smb[];
    __nv_bfloat16* Qs  = smb;                    // [256][SQ]
    __nv_bfloat16* Ks  = Qs + 256 * SQ;          // [256][SQ]
    __nv_bfloat16* VsT = Ks + 256 * SQ;          // [32][SV]
    float* ms = (float*)(VsT + 32 * SV);         // [256]
    const int i = blockIdx.x, h = blockIdx.y;
    const int tid = threadIdx.x;
    const int warp = tid >> 5, lane = tid & 31;

    const size_t base = (size_t)(i * N_HEADS + h) * N_POS * C_DIM;
    // Q, K (vectorized)
    for (int idx = tid; idx < 1024; idx += 128) {
        const int j = idx >> 2, seg = idx & 3;
        *(uint4*)(Qs + j * SQ + seg * 8) = *(const uint4*)(g_qb + base + j * 32 + seg * 8);
        *(uint4*)(Ks + j * SQ + seg * 8) = *(const uint4*)(g_kb + base + j * 32 + seg * 8);
    }
    // V transposed
    for (int idx = tid; idx < 8192; idx += 128) {
        const int j = idx >> 5, c = idx & 31;
        VsT[c * SV + j] = g_vb[base + idx];
    }
    for (int kk = tid; kk < 256; kk += 128)
        ms[kk] = 1e9f * (__ldg(Z_mask + i * N_POS + kk) - 1.0f);
    __syncthreads();

    const float* trib = g_trib + (size_t)h * ROWS;

    for (int chunk = 0; chunk < 4; chunk++) {
        const int R  = chunk * 64 + warp * 16;
        const int r0 = R + (lane >> 2);
        const int r1 = r0 + 8;

        // Q fragments (2 k-iters over c=32)
        unsigned qa[2][4];
        #pragma unroll
        for (int kt = 0; kt < 2; kt++) {
            const __nv_bfloat16* a0 = Qs + r0 * SQ + kt * 16 + (lane & 3) * 2;
            const __nv_bfloat16* a1 = Qs + r1 * SQ + kt * 16 + (lane & 3) * 2;
            qa[kt][0] = *(const unsigned*)a0;
            qa[kt][1] = *(const unsigned*)a1;
            qa[kt][2] = *(const unsigned*)(a0 + 8);
            qa[kt][3] = *(const unsigned*)(a1 + 8);
        }

        // S accumulator initialized with mask + triangle bias
        float sacc[32][4];
        const float* tq0 = trib + (size_t)r0 * 256;
        const float* tq1 = trib + (size_t)r1 * 256;
        #pragma unroll
        for (int nt = 0; nt < 32; nt++) {
            const int col = nt * 8 + (lane & 3) * 2;
            const float2 t0 = *(const float2*)(tq0 + col);
            const float2 t1 = *(const float2*)(tq1 + col);
            const float m0 = ms[col], m1 = ms[col + 1];
            sacc[nt][0] = t0.x + m0; sacc[nt][1] = t0.y + m1;
            sacc[nt][2] = t1.x + m0; sacc[nt][3] = t1.y + m1;
        }

        // S = Q K^T
        #pragma unroll
        for (int nt = 0; nt < 32; nt++) {
            const __nv_bfloat16* kp = Ks + (nt * 8 + (lane >> 2)) * SQ + (lane & 3) * 2;
            unsigned b0[2] = { *(const unsigned*)kp,        *(const unsigned*)(kp + 8) };
            mma_bf16(sacc[nt], qa[0], b0);
            unsigned b1[2] = { *(const unsigned*)(kp + 16), *(const unsigned*)(kp + 24) };
            mma_bf16(sacc[nt], qa[1], b1);
        }

        // softmax (rows r0 via c0,c1; r1 via c2,c3); quad = lanes sharing lane>>2
        float mx0 = -3.0e38f, mx1 = -3.0e38f;
        #pragma unroll
        for (int nt = 0; nt < 32; nt++) {
            mx0 = fmaxf(mx0, fmaxf(sacc[nt][0], sacc[nt][1]));
            mx1 = fmaxf(mx1, fmaxf(sacc[nt][2], sacc[nt][3]));
        }
        mx0 = fmaxf(mx0, __shfl_xor_sync(0xffffffffu, mx0, 1));
        mx0 = fmaxf(mx0, __shfl_xor_sync(0xffffffffu, mx0, 2));
        mx1 = fmaxf(mx1, __shfl_xor_sync(0xffffffffu, mx1, 1));
        mx1 = fmaxf(mx1, __shfl_xor_sync(0xffffffffu, mx1, 2));
        float s0 = 0.0f, s1 = 0.0f;
        #pragma unroll
        for (int nt = 0; nt < 32; nt++) {
            sacc[nt][0] = __expf(sacc[nt][0] - mx0); s0 += sacc[nt][0];
            sacc[nt][1] = __expf(sacc[nt][1] - mx0); s0 += sacc[nt][1];
            sacc[nt][2] = __expf(sacc[nt][2] - mx1); s1 += sacc[nt][2];
            sacc[nt][3] = __expf(sacc[nt][3] - mx1); s1 += sacc[nt][3];
        }
        s0 += __shfl_xor_sync(0xffffffffu, s0, 1);
        s0 += __shfl_xor_sync(0xffffffffu, s0, 2);
        s1 += __shfl_xor_sync(0xffffffffu, s1, 1);
        s1 += __shfl_xor_sync(0xffffffffu, s1, 2);
        const float inv0 = 1.0f / s0, inv1 = 1.0f / s1;

        // O = P V (P passed in registers: S-acc layout == A-frag layout)
        float oacc[4][4];
        #pragma unroll
        for (int vt = 0; vt < 4; vt++)
            #pragma unroll
            for (int j = 0; j < 4; j++) oacc[vt][j] = 0.0f;

        #pragma unroll
        for (int kt = 0; kt < 16; kt++) {
            unsigned pa[4];
            pa[0] = pack_bf16(sacc[2 * kt][0],     sacc[2 * kt][1]);
            pa[1] = pack_bf16(sacc[2 * kt][2],     sacc[2 * kt][3]);
            pa[2] = pack_bf16(sacc[2 * kt + 1][0], sacc[2 * kt + 1][1]);
            pa[3] = pack_bf16(sacc[2 * kt + 1][2], sacc[2 * kt + 1][3]);
            #pragma unroll
            for (int vt = 0; vt < 4; vt++) {
                const __nv_bfloat16* vp =
                    VsT + (vt * 8 + (lane >> 2)) * SV + kt * 16 + (lane & 3) * 2;
                unsigned b[2] = { *(const unsigned*)vp, *(const unsigned*)(vp + 8) };
                mma_bf16(oacc[vt], pa, b);
            }
        }

        // epilogue: normalize, gate, store bf16
        const size_t grow0 = (size_t)i * 256 + r0;
        const size_t grow1 = (size_t)i * 256 + r1;
        #pragma unroll
        for (int vt = 0; vt < 4; vt++) {
            const int col  = vt * 8 + (lane & 3) * 2;
            const int gcol = h * 32 + col;
            const float2 bgv = *(const float2*)(bg + gcol);
            const float2 gg0 = *(const float2*)(g_g + grow0 * D_DIM + gcol);
            const float2 gg1 = *(const float2*)(g_g + grow1 * D_DIM + gcol);
            const float gt00 = 1.0f / (1.0f + __expf(-(gg0.x + bgv.x)));
            const float gt01 = 1.0f / (1.0f + __expf(-(gg0.y + bgv.y)));
            const float gt10 = 1.0f / (1.0f + __expf(-(gg1.x + bgv.x)));
            const float gt11 = 1.0f / (1.0f + __expf(-(gg1.y + bgv.y)));
            *(__nv_bfloat162*)(g_ogb + grow0 * D_DIM + gcol) =
                __float22bfloat162_rn(make_float2(oacc[vt][0] * inv0 * gt00,
                                                  oacc[vt][1] * inv0 * gt01));
            *(__nv_bfloat162*)(g_ogb + grow1 * D_DIM + gcol) =
                __float22bfloat162_rn(make_float2(oacc[vt][2] * inv1 * gt10,
                                                  oacc[vt][3] * inv1 * gt11));
        }
    }
}

// ---------------- kernel 3: output projection + bias + residual ----------------
__global__ __launch_bounds__(256) void k_out(
    const float* __restrict__ Z_raw,
    const float* __restrict__ out_bias, float* __restrict__ out)
{
    extern __shared__ __nv_bfloat16 smb[];
    __nv_bfloat16* os = smb;                 // [64][SA]
    __nv_bfloat16* ws = smb + 64 * SA;       // [128][SA]
    const int tid  = threadIdx.x;
    const int row0 = blockIdx.x * 64;
    const int warp = tid >> 5, lane = tid & 31;

    for (int idx = tid; idx < 1024; idx += 256) {
        const int r = idx >> 4, seg = idx & 15;
        *(uint4*)(os + r * SA + seg * 8) =
            *(const uint4*)(g_ogb + (size_t)(row0 + r) * D_DIM + seg * 8);
    }
    for (int idx = tid; idx < 2048; idx += 256) {
        const int n = idx >> 4, seg = idx & 15;
        *(uint4*)(ws + n * SA + seg * 8) = *(const uint4*)(g_woT + n * 128 + seg * 8);
    }
    __syncthreads();

    const int warp_m = warp & 3, warp_n = warp >> 2;
    const int r0 = warp_m * 16 + (lane >> 2);
    const int r1 = r0 + 8;

    unsigned afr[8][4];
    #pragma unroll
    for (int kt = 0; kt < 8; kt++) {
        const __nv_bfloat16* a0 = os + r0 * SA + kt * 16 + (lane & 3) * 2;
        const __nv_bfloat16* a1 = os + r1 * SA + kt * 16 + (lane & 3) * 2;
        afr[kt][0] = *(const unsigned*)a0;
        afr[kt][1] = *(const unsigned*)a1;
        afr[kt][2] = *(const unsigned*)(a0 + 8);
        afr[kt][3] = *(const unsigned*)(a1 + 8);
    }

    float acc[8][4];
    #pragma unroll
    for (int nt = 0; nt < 8; nt++)
        #pragma unroll
        for (int j = 0; j < 4; j++) acc[nt][j] = 0.0f;

    #pragma unroll
    for (int kt = 0; kt < 8; kt++) {
        #pragma unroll
        for (int nt = 0; nt < 8; nt++) {
            const __nv_bfloat16* bp =
                ws + (warp_n * 64 + nt * 8 + (lane >> 2)) * SA + kt * 16 + (lane & 3) * 2;
            unsigned b[2] = { *(const unsigned*)bp, *(const unsigned*)(bp + 8) };
            mma_bf16(acc[nt], afr[kt], b);
        }
    }

    const size_t gr0 = row0 + r0, gr1 = row0 + r1;
    #pragma unroll
    for (int nt = 0; nt < 8; nt++) {
        const int col = warp_n * 64 + nt * 8 + (lane & 3) * 2;
        const float2 ob = *(const float2*)(out_bias + col);
        const float2 z0 = *(const float2*)(Z_raw + gr0 * D_DIM + col);
        const float2 z1 = *(const float2*)(Z_raw + gr1 * D_DIM + col);
        *(float2*)(out + gr0 * D_DIM + col) =
            make_float2(acc[nt][0] + ob.x + z0.x, acc[nt][1] + ob.y + z0.y);
        *(float2*)(out + gr1 * D_DIM + col) =
            make_float2(acc[nt][2] + ob.x + z1.x, acc[nt][3] + ob.y + z1.y);
    }
}

// ---------------------------------------------------------------------------
extern "C" void kernel_launch(void* const* d_in, const int* in_sizes, int n_in,
                              void* d_out, int out_size)
{
    (void)in_sizes; (void)n_in; (void)out_size;
    const float* Z_raw    = (const float*)d_in[0];
    const float* Z_mask   = (const float*)d_in[1];
    const float* ln_w     = (const float*)d_in[2];
    const float* ln_b     = (const float*)d_in[3];
    const float* w_b      = (const float*)d_in[4];
    const float* wq       = (const float*)d_in[5];
    const float* wk       = (const float*)d_in[6];
    const float* wv       = (const float*)d_in[7];
    const float* wg       = (const float*)d_in[8];
    const float* bg       = (const float*)d_in[9];
    const float* wo       = (const float*)d_in[10];
    const float* out_bias = (const float*)d_in[11];
    float* out = (float*)d_out;

    const int smem_gemm = (64 * SA + 128 * SA) * 2;                        // 52224
    const int smem_attn = (2 * 256 * SQ + 32 * SV) * 2 + 256 * 4;          // 58880

    cudaFuncSetAttribute(k_proj, cudaFuncAttributeMaxDynamicSharedMemorySize, smem_gemm);
    cudaFuncSetAttribute(k_attn, cudaFuncAttributeMaxDynamicSharedMemorySize, smem_attn);
    cudaFuncSetAttribute(k_out,  cudaFuncAttributeMaxDynamicSharedMemorySize, smem_gemm);

    k_setup<<<320, 256>>>(wq, wk, wv, wg, wo);
    k_proj<<<ROWS / 64, 256, smem_gemm>>>(Z_raw, ln_w, ln_b, w_b);
    k_attn<<<dim3(N_POS, N_HEADS), 128, smem_attn>>>(Z_mask, bg);
    k_out<<<ROWS / 64, 256, smem_gemm>>>(Z_raw, out_bias, out);
}

// round 6
// speedup vs baseline: 6.6762x; 1.6861x over previous
#include <cuda_runtime.h>
#include <cuda_bf16.h>
#include <math.h>

#define N_POS 256
#define D_DIM 128
#define N_HEADS 4
#define C_DIM 32
#define ROWS (N_POS * N_POS)   // 65536

// ---------------- scratch (static device arrays) ----------------
__device__ __nv_bfloat16 g_qb[N_POS * N_HEADS * N_POS * C_DIM];   // [i][h][j][c]
__device__ __nv_bfloat16 g_kb[N_POS * N_HEADS * N_POS * C_DIM];   // [i][h][j][c]
__device__ __nv_bfloat16 g_vT[N_POS * N_HEADS * C_DIM * N_POS];   // [i][h][c][j]
__device__ __nv_bfloat16 g_gb[N_POS * N_HEADS * N_POS * C_DIM];   // sigmoid gate [i][h][j][c]
__device__ __nv_bfloat16 g_ogb[ROWS * D_DIM];                     // gated attn out (bf16)
__device__ __nv_bfloat16 g_trib[N_HEADS * ROWS];                  // [h][q*256+k] bf16
__device__ __nv_bfloat16 g_wT[4][D_DIM * D_DIM];                  // q,k,v,g as [n][k] bf16
__device__ __nv_bfloat16 g_woT[D_DIM * D_DIM];                    // [d][hc] bf16

// ---------------- mma helper ----------------
__device__ __forceinline__ void mma_bf16(float* c, const unsigned* a, const unsigned* b) {
    asm volatile(
        "mma.sync.aligned.m16n8k16.row.col.f32.bf16.bf16.f32 "
        "{%0,%1,%2,%3}, {%4,%5,%6,%7}, {%8,%9}, {%0,%1,%2,%3};\n"
        : "+f"(c[0]), "+f"(c[1]), "+f"(c[2]), "+f"(c[3])
        : "r"(a[0]), "r"(a[1]), "r"(a[2]), "r"(a[3]), "r"(b[0]), "r"(b[1]));
}

__device__ __forceinline__ unsigned pack_bf16(float lo, float hi) {
    __nv_bfloat162 t = __float22bfloat162_rn(make_float2(lo, hi));
    return *(unsigned*)&t;
}

// ---------------- kernel 0: weight transpose to bf16 ----------------
__global__ __launch_bounds__(256) void k_setup(
    const float* __restrict__ wq, const float* __restrict__ wk,
    const float* __restrict__ wv, const float* __restrict__ wg,
    const float* __restrict__ wo)
{
    int idx = blockIdx.x * 256 + threadIdx.x;
    if (idx >= 5 * 16384) return;
    const int m = idx >> 14, r = idx & 16383;
    const int k = r >> 7, n = r & 127;
    const float* src = (m == 0) ? wq : (m == 1) ? wk : (m == 2) ? wv : (m == 3) ? wg : wo;
    float v = src[r];
    if (m == 0) v *= 0.17677669529663687f;   // c^-0.5 folded into wq
    __nv_bfloat16 bv = __float2bfloat16(v);
    if (m < 4) g_wT[m][n * 128 + k] = bv;
    else       g_woT[n * 128 + k] = bv;
}

// ---------------- kernel 1: LN + 4 projections + triangle bias ----------------
#define SA 136   // bf16 row stride (GEMM smem)
#define VST 72   // V staging stride (bf16), 16B-aligned rows
__global__ __launch_bounds__(256) void k_proj(
    const float* __restrict__ Z_raw,
    const float* __restrict__ ln_w, const float* __restrict__ ln_b,
    const float* __restrict__ w_b, const float* __restrict__ bg)
{
    extern __shared__ __nv_bfloat16 smb[];
    __nv_bfloat16* zn = smb;                 // [64][SA]
    __nv_bfloat16* ws = smb + 64 * SA;       // [128][SA]  (also V-transpose staging)
    const int tid  = threadIdx.x;
    const int row0 = blockIdx.x * 64;
    const int warp = tid >> 5, lane = tid & 31;

    // --- LayerNorm -> bf16 smem ---
    for (int r = warp; r < 64; r += 8) {
        const float4 x = ((const float4*)(Z_raw + (size_t)(row0 + r) * D_DIM))[lane];
        float s  = x.x + x.y + x.z + x.w;
        float ss = x.x * x.x + x.y * x.y + x.z * x.z + x.w * x.w;
        #pragma unroll
        for (int o = 16; o > 0; o >>= 1) {
            s  += __shfl_xor_sync(0xffffffffu, s, o);
            ss += __shfl_xor_sync(0xffffffffu, ss, o);
        }
        const float mu  = s * (1.0f / 128.0f);
        const float inv = rsqrtf(ss * (1.0f / 128.0f) - mu * mu + 1e-5f);
        const int c = lane * 4;
        float v0 = (x.x - mu) * inv * __ldg(ln_w + c + 0) + __ldg(ln_b + c + 0);
        float v1 = (x.y - mu) * inv * __ldg(ln_w + c + 1) + __ldg(ln_b + c + 1);
        float v2 = (x.z - mu) * inv * __ldg(ln_w + c + 2) + __ldg(ln_b + c + 2);
        float v3 = (x.w - mu) * inv * __ldg(ln_w + c + 3) + __ldg(ln_b + c + 3);
        __nv_bfloat162* zr = (__nv_bfloat162*)(zn + r * SA + c);
        zr[0] = __float22bfloat162_rn(make_float2(v0, v1));
        zr[1] = __float22bfloat162_rn(make_float2(v2, v3));
    }
    __syncthreads();

    // --- triangle bias (bf16 out) ---
    {
        const int r = tid >> 2, h = tid & 3;
        float acc = 0.0f;
        #pragma unroll 8
        for (int kk = 0; kk < D_DIM; kk++)
            acc = fmaf(__bfloat162float(zn[r * SA + kk]), __ldg(w_b + kk * N_HEADS + h), acc);
        g_trib[h * ROWS + row0 + r] = __float2bfloat16(acc);
    }

    // --- A fragments (reused across all 4 weight matrices) ---
    const int warp_m = warp & 3, warp_n = warp >> 2;
    const int r0 = warp_m * 16 + (lane >> 2);   // local row 0..63
    const int r1 = r0 + 8;
    unsigned afr[8][4];
    #pragma unroll
    for (int kt = 0; kt < 8; kt++) {
        const __nv_bfloat16* a0 = zn + r0 * SA + kt * 16 + (lane & 3) * 2;
        const __nv_bfloat16* a1 = zn + r1 * SA + kt * 16 + (lane & 3) * 2;
        afr[kt][0] = *(const unsigned*)a0;
        afr[kt][1] = *(const unsigned*)a1;
        afr[kt][2] = *(const unsigned*)(a0 + 8);
        afr[kt][3] = *(const unsigned*)(a1 + 8);
    }

    const int iblk = row0 >> 8, jbase = row0 & 255;

    for (int m = 0; m < 4; m++) {
        __syncthreads();
        const __nv_bfloat16* Wsrc = g_wT[m];
        for (int idx = tid; idx < 2048; idx += 256) {
            const int n = idx >> 4, seg = idx & 15;
            *(uint4*)(ws + n * SA + seg * 8) = *(const uint4*)(Wsrc + n * 128 + seg * 8);
        }
        __syncthreads();

        float acc[8][4];
        #pragma unroll
        for (int nt = 0; nt < 8; nt++)
            #pragma unroll
            for (int j = 0; j < 4; j++) acc[nt][j] = 0.0f;

        #pragma unroll
        for (int kt = 0; kt < 8; kt++) {
            #pragma unroll
            for (int nt = 0; nt < 8; nt++) {
                const __nv_bfloat16* bp =
                    ws + (warp_n * 64 + nt * 8 + (lane >> 2)) * SA + kt * 16 + (lane & 3) * 2;
                unsigned b[2] = { *(const unsigned*)bp, *(const unsigned*)(bp + 8) };
                mma_bf16(acc[nt], afr[kt], b);
            }
        }

        if (m == 2) {
            // stage V transposed through smem (reuse ws; wv no longer needed)
            __syncthreads();
            #pragma unroll
            for (int nt = 0; nt < 8; nt++) {
                const int col = warp_n * 64 + nt * 8 + (lane & 3) * 2;
                ws[col * VST + r0]       = __float2bfloat16(acc[nt][0]);
                ws[(col + 1) * VST + r0] = __float2bfloat16(acc[nt][1]);
                ws[col * VST + r1]       = __float2bfloat16(acc[nt][2]);
                ws[(col + 1) * VST + r1] = __float2bfloat16(acc[nt][3]);
            }
            __syncthreads();
            for (int idx = tid; idx < 1024; idx += 256) {
                const int col = idx >> 3, seg = idx & 7;
                *(uint4*)(g_vT + (((size_t)iblk * 4 + (col >> 5)) * 32 + (col & 31)) * 256
                          + jbase + seg * 8) =
                    *(const uint4*)(ws + col * VST + seg * 8);
            }
        } else {
            const int gr0 = row0 + r0, gr1 = row0 + r1;
            #pragma unroll
            for (int nt = 0; nt < 8; nt++) {
                const int col = warp_n * 64 + nt * 8 + (lane & 3) * 2;
                const int h = col >> 5, c = col & 31;
                const int j0 = gr0 & 255, j1 = gr1 & 255;
                if (m < 2) {
                    __nv_bfloat16* dst = (m == 0) ? g_qb : g_kb;
                    *(__nv_bfloat162*)(dst + ((iblk * 4 + h) * 256 + j0) * 32 + c) =
                        __float22bfloat162_rn(make_float2(acc[nt][0], acc[nt][1]));
                    *(__nv_bfloat162*)(dst + ((iblk * 4 + h) * 256 + j1) * 32 + c) =
                        __float22bfloat162_rn(make_float2(acc[nt][2], acc[nt][3]));
                } else {
                    // gate: sigmoid(acc + bg), store bf16
                    const float2 bgv = __ldg((const float2*)(bg + col));
                    const float g00 = 1.0f / (1.0f + __expf(-(acc[nt][0] + bgv.x)));
                    const float g01 = 1.0f / (1.0f + __expf(-(acc[nt][1] + bgv.y)));
                    const float g10 = 1.0f / (1.0f + __expf(-(acc[nt][2] + bgv.x)));
                    const float g11 = 1.0f / (1.0f + __expf(-(acc[nt][3] + bgv.y)));
                    *(__nv_bfloat162*)(g_gb + ((iblk * 4 + h) * 256 + j0) * 32 + c) =
                        __float22bfloat162_rn(make_float2(g00, g01));
                    *(__nv_bfloat162*)(g_gb + ((iblk * 4 + h) * 256 + j1) * 32 + c) =
                        __float22bfloat162_rn(make_float2(g10, g11));
                }
            }
        }
    }
}

// ---------------- kernel 2: attention per (i,h) ----------------
// K-tiled (2 x 128), no max-subtraction (logits are O(1); exp(-1e9)=0 for mask).
#define SK 40     // Ks bf16 row stride
#define SV 264    // VsT bf16 row stride
__global__ __launch_bounds__(128, 4) void k_attn(const float* __restrict__ Z_mask)
{
    extern __shared__ __nv_bfloat16 smb[];
    __nv_bfloat16* Ks  = smb;                    // [256][SK]
    __nv_bfloat16* VsT = Ks + 256 * SK;          // [32][SV]
    float* ms = (float*)(VsT + 32 * SV);         // [256]
    const int i = blockIdx.x, h = blockIdx.y;
    const int tid = threadIdx.x;
    const int warp = tid >> 5, lane = tid & 31;

    const size_t base = (size_t)(i * N_HEADS + h) * N_POS * C_DIM;
    for (int idx = tid; idx < 1024; idx += 128) {
        const int j = idx >> 2, seg = idx & 3;
        *(uint4*)(Ks + j * SK + seg * 8) = *(const uint4*)(g_kb + base + j * 32 + seg * 8);
    }
    for (int idx = tid; idx < 1024; idx += 128) {
        const int c = idx >> 5, seg = idx & 31;
        *(uint4*)(VsT + c * SV + seg * 8) = *(const uint4*)(g_vT + base + c * 256 + seg * 8);
    }
    for (int kk = tid; kk < 256; kk += 128)
        ms[kk] = 1e9f * (__ldg(Z_mask + i * N_POS + kk) - 1.0f);
    __syncthreads();

    const __nv_bfloat16* tribh = g_trib + (size_t)h * ROWS;
    const int qt = (lane & 3) * 2;

    for (int chunk = 0; chunk < 4; chunk++) {
        const int r0 = chunk * 64 + warp * 16 + (lane >> 2);
        const int r1 = r0 + 8;

        // Q fragments straight from global (each q element used exactly once)
        unsigned qa[2][4];
        {
            const __nv_bfloat16* q0 = g_qb + base + (size_t)r0 * 32 + qt;
            const __nv_bfloat16* q1 = g_qb + base + (size_t)r1 * 32 + qt;
            #pragma unroll
            for (int kt = 0; kt < 2; kt++) {
                qa[kt][0] = *(const unsigned*)(q0 + kt * 16);
                qa[kt][1] = *(const unsigned*)(q1 + kt * 16);
                qa[kt][2] = *(const unsigned*)(q0 + kt * 16 + 8);
                qa[kt][3] = *(const unsigned*)(q1 + kt * 16 + 8);
            }
        }

        float oacc[4][4];
        #pragma unroll
        for (int vt = 0; vt < 4; vt++)
            #pragma unroll
            for (int j = 0; j < 4; j++) oacc[vt][j] = 0.0f;
        float s0 = 0.0f, s1 = 0.0f;

        const __nv_bfloat16* t0p = tribh + (size_t)r0 * 256;
        const __nv_bfloat16* t1p = tribh + (size_t)r1 * 256;

        #pragma unroll
        for (int kb = 0; kb < 2; kb++) {
            float sacc[16][4];
            // init with trib + mask
            #pragma unroll
            for (int nt = 0; nt < 16; nt++) {
                const int col = kb * 128 + nt * 8 + qt;
                const float2 tb0 = __bfloat1622float2(*(const __nv_bfloat162*)(t0p + col));
                const float2 tb1 = __bfloat1622float2(*(const __nv_bfloat162*)(t1p + col));
                const float2 mv  = *(const float2*)(ms + col);
                sacc[nt][0] = tb0.x + mv.x; sacc[nt][1] = tb0.y + mv.y;
                sacc[nt][2] = tb1.x + mv.x; sacc[nt][3] = tb1.y + mv.y;
            }
            // S = Q K^T
            #pragma unroll
            for (int nt = 0; nt < 16; nt++) {
                const __nv_bfloat16* kp =
                    Ks + (kb * 128 + nt * 8 + (lane >> 2)) * SK + qt;
                unsigned b0[2] = { *(const unsigned*)kp,        *(const unsigned*)(kp + 8) };
                mma_bf16(sacc[nt], qa[0], b0);
                unsigned b1[2] = { *(const unsigned*)(kp + 16), *(const unsigned*)(kp + 24) };
                mma_bf16(sacc[nt], qa[1], b1);
            }
            // P = exp(S), accumulate sums
            #pragma unroll
            for (int nt = 0; nt < 16; nt++) {
                sacc[nt][0] = __expf(sacc[nt][0]); s0 += sacc[nt][0];
                sacc[nt][1] = __expf(sacc[nt][1]); s0 += sacc[nt][1];
                sacc[nt][2] = __expf(sacc[nt][2]); s1 += sacc[nt][2];
                sacc[nt][3] = __expf(sacc[nt][3]); s1 += sacc[nt][3];
            }
            // O += P V
            #pragma unroll
            for (int kt = 0; kt < 8; kt++) {
                unsigned pa[4];
                pa[0] = pack_bf16(sacc[2 * kt][0],     sacc[2 * kt][1]);
                pa[1] = pack_bf16(sacc[2 * kt][2],     sacc[2 * kt][3]);
                pa[2] = pack_bf16(sacc[2 * kt + 1][0], sacc[2 * kt + 1][1]);
                pa[3] = pack_bf16(sacc[2 * kt + 1][2], sacc[2 * kt + 1][3]);
                #pragma unroll
                for (int vt = 0; vt < 4; vt++) {
                    const __nv_bfloat16* vp =
                        VsT + (vt * 8 + (lane >> 2)) * SV + kb * 128 + kt * 16 + qt;
                    unsigned b[2] = { *(const unsigned*)vp, *(const unsigned*)(vp + 8) };
                    mma_bf16(oacc[vt], pa, b);
                }
            }
        }

        s0 += __shfl_xor_sync(0xffffffffu, s0, 1);
        s0 += __shfl_xor_sync(0xffffffffu, s0, 2);
        s1 += __shfl_xor_sync(0xffffffffu, s1, 1);
        s1 += __shfl_xor_sync(0xffffffffu, s1, 2);
        const float inv0 = 1.0f / s0, inv1 = 1.0f / s1;

        // epilogue: normalize, gate (precomputed sigmoid, bf16), store bf16
        const size_t grow0 = (size_t)i * 256 + r0;
        const size_t grow1 = (size_t)i * 256 + r1;
        #pragma unroll
        for (int vt = 0; vt < 4; vt++) {
            const int colc = vt * 8 + qt;            // 0..31 within head
            const float2 gv0 = __bfloat1622float2(
                *(const __nv_bfloat162*)(g_gb + base + (size_t)r0 * 32 + colc));
            const float2 gv1 = __bfloat1622float2(
                *(const __nv_bfloat162*)(g_gb + base + (size_t)r1 * 32 + colc));
            *(__nv_bfloat162*)(g_ogb + grow0 * D_DIM + h * 32 + colc) =
                __float22bfloat162_rn(make_float2(oacc[vt][0] * inv0 * gv0.x,
                                                  oacc[vt][1] * inv0 * gv0.y));
            *(__nv_bfloat162*)(g_ogb + grow1 * D_DIM + h * 32 + colc) =
                __float22bfloat162_rn(make_float2(oacc[vt][2] * inv1 * gv1.x,
                                                  oacc[vt][3] * inv1 * gv1.y));
        }
    }
}

// ---------------- kernel 3: output projection + bias + residual ----------------
// 2 tiles of 64 rows per block; weight load amortized.
__global__ __launch_bounds__(256) void k_out(
    const float* __restrict__ Z_raw,
    const float* __restrict__ out_bias, float* __restrict__ out)
{
    extern __shared__ __nv_bfloat16 smb[];
    __nv_bfloat16* os = smb;                 // [64][SA]
    __nv_bfloat16* ws = smb + 64 * SA;       // [128][SA]
    const int tid  = threadIdx.x;
    const int warp = tid >> 5, lane = tid & 31;
    const int warp_m = warp & 3, warp_n = warp >> 2;
    const int lr0 = warp_m * 16 + (lane >> 2);
    const int lr1 = lr0 + 8;

    for (int idx = tid; idx < 2048; idx += 256) {
        const int n = idx >> 4, seg = idx & 15;
        *(uint4*)(ws + n * SA + seg * 8) = *(const uint4*)(g_woT + n * 128 + seg * 8);
    }

    for (int t = 0; t < 2; t++) {
        const int row0 = blockIdx.x * 128 + t * 64;
        __syncthreads();
        for (int idx = tid; idx < 1024; idx += 256) {
            const int r = idx >> 4, seg = idx & 15;
            *(uint4*)(os + r * SA + seg * 8) =
                *(const uint4*)(g_ogb + (size_t)(row0 + r) * D_DIM + seg * 8);
        }
        __syncthreads();

        unsigned afr[8][4];
        #pragma unroll
        for (int kt = 0; kt < 8; kt++) {
            const __nv_bfloat16* a0 = os + lr0 * SA + kt * 16 + (lane & 3) * 2;
            const __nv_bfloat16* a1 = os + lr1 * SA + kt * 16 + (lane & 3) * 2;
            afr[kt][0] = *(const unsigned*)a0;
            afr[kt][1] = *(const unsigned*)a1;
            afr[kt][2] = *(const unsigned*)(a0 + 8);
            afr[kt][3] = *(const unsigned*)(a1 + 8);
        }

        float acc[8][4];
        #pragma unroll
        for (int nt = 0; nt < 8; nt++)
            #pragma unroll
            for (int j = 0; j < 4; j++) acc[nt][j] = 0.0f;

        #pragma unroll
        for (int kt = 0; kt < 8; kt++) {
            #pragma unroll
            for (int nt = 0; nt < 8; nt++) {
                const __nv_bfloat16* bp =
                    ws + (warp_n * 64 + nt * 8 + (lane >> 2)) * SA + kt * 16 + (lane & 3) * 2;
                unsigned b[2] = { *(const unsigned*)bp, *(const unsigned*)(bp + 8) };
                mma_bf16(acc[nt], afr[kt], b);
            }
        }

        const size_t gr0 = row0 + lr0, gr1 = row0 + lr1;
        #pragma unroll
        for (int nt = 0; nt < 8; nt++) {
            const int col = warp_n * 64 + nt * 8 + (lane & 3) * 2;
            const float2 ob = *(const float2*)(out_bias + col);
            const float2 z0 = *(const float2*)(Z_raw + gr0 * D_DIM + col);
            const float2 z1 = *(const float2*)(Z_raw + gr1 * D_DIM + col);
            *(float2*)(out + gr0 * D_DIM + col) =
                make_float2(acc[nt][0] + ob.x + z0.x, acc[nt][1] + ob.y + z0.y);
            *(float2*)(out + gr1 * D_DIM + col) =
                make_float2(acc[nt][2] + ob.x + z1.x, acc[nt][3] + ob.y + z1.y);
        }
    }
}

// ---------------------------------------------------------------------------
extern "C" void kernel_launch(void* const* d_in, const int* in_sizes, int n_in,
                              void* d_out, int out_size)
{
    (void)in_sizes; (void)n_in; (void)out_size;
    const float* Z_raw    = (const float*)d_in[0];
    const float* Z_mask   = (const float*)d_in[1];
    const float* ln_w     = (const float*)d_in[2];
    const float* ln_b     = (const float*)d_in[3];
    const float* w_b      = (const float*)d_in[4];
    const float* wq       = (const float*)d_in[5];
    const float* wk       = (const float*)d_in[6];
    const float* wv       = (const float*)d_in[7];
    const float* wg       = (const float*)d_in[8];
    const float* bg       = (const float*)d_in[9];
    const float* wo       = (const float*)d_in[10];
    const float* out_bias = (const float*)d_in[11];
    float* out = (float*)d_out;

    const int smem_gemm = (64 * SA + 128 * SA) * 2;                    // 52224
    const int smem_attn = (256 * SK + 32 * SV) * 2 + 256 * 4;          // 38400

    cudaFuncSetAttribute(k_proj, cudaFuncAttributeMaxDynamicSharedMemorySize, smem_gemm);
    cudaFuncSetAttribute(k_attn, cudaFuncAttributeMaxDynamicSharedMemorySize, smem_attn);
    cudaFuncSetAttribute(k_out,  cudaFuncAttributeMaxDynamicSharedMemorySize, smem_gemm);

    k_setup<<<320, 256>>>(wq, wk, wv, wg, wo);
    k_proj<<<ROWS / 64, 256, smem_gemm>>>(Z_raw, ln_w, ln_b, w_b, bg);
    k_attn<<<dim3(N_POS, N_HEADS), 128, smem_attn>>>(Z_mask);
    k_out<<<ROWS / 128, 256, smem_gemm>>>(Z_raw, out_bias, out);
}